// round 11
// baseline (speedup 1.0000x reference)
#include <cuda_runtime.h>
#include <math.h>

// Problem constants
#define Bz 64
#define Oz 32
#define Iz 2048
#define Dz 16   // DOUT == DIN == 16

// ---------------- scratch (static device globals; no allocation) ----------------
// u_hat layout: [b][o][i][d]  (d contiguous -> coalesced float2 stores in k_uhat,
// per-thread contiguous 64B reads in k_sd/k_s_final)
__device__ float g_uhat[(size_t)Bz * Oz * Iz * Dz];   // 256 MiB
__device__ float g_d[(size_t)Bz * Oz * Iz];           // distances d[b][o][i]
__device__ float g_c[(size_t)Bz * Oz * Iz];           // routing coeffs (iter-1 scratch)
__device__ float g_partial[Bz * Oz];                  // per-CTA partial sums of d
__device__ float g_unorm[(size_t)Bz * Iz];            // ||u[b,i]|| (precomputed)

// =======================================================================
// k_unorm: ||u[b,i]|| for all (b,i). 128K threads, trivially coalesced.
// =======================================================================
__global__ __launch_bounds__(256) void k_unorm(const float* __restrict__ u)
{
    const int idx = blockIdx.x * 256 + threadIdx.x;   // b*Iz + i
    const float4* up = (const float4*)(u + (size_t)idx * 16);
    float n2 = 0.f;
    #pragma unroll
    for (int q = 0; q < 4; q++) {
        float4 t = up[q];
        n2 += t.x*t.x + t.y*t.y + t.z*t.z + t.w*t.w;
    }
    g_unorm[idx] = sqrtf(n2);
}

// =======================================================================
// K1: u_hat[b,o,i,d] = clip( sum_k W[o,i,d,k] * u[b,i,k] )
// Grid: (I/32, O). Block: 256 = 8 warps; lane = il_local*8 + dg.
//   warp w covers i = i0 + 4w .. i0+4w+3 (il_local 0..3), dg = 2-row d-group.
// W rows for this thread's 2 d's live in REGISTERS (32 floats, loaded once).
// u staged to smem in 16-batch chunks; inner LDS.128 are 8-lane broadcasts.
// Norm over d reduced with 3 shfl_xor inside the 8-lane dg group.
// Output layout [b][o][i][d]: thread's 2 outputs adjacent -> STG.64; warp's
// 32 lanes cover a contiguous 256B run -> fully coalesced stores.
// =======================================================================
__global__ __launch_bounds__(256) void k_uhat(const float* __restrict__ u,
                                              const float* __restrict__ W)
{
    __shared__ float pool[32 * 264];        // 33.8 KB: W staging, then u chunks
    __shared__ float un_sm[512];            // ||u|| for current chunk (16b x 32i)

    const int o  = blockIdx.y;
    const int i0 = blockIdx.x * 32;
    const int tid  = threadIdx.x;
    const int w    = tid >> 5;
    const int lane = tid & 31;
    const int il_l = lane >> 3;             // 0..3
    const int dg   = lane & 7;              // 0..7 -> d rows 2dg, 2dg+1
    const int il   = w * 4 + il_l;          // 0..31
    const int i    = i0 + il;

    // ---- stage W[o, i0..i0+31, :, :] (8192 contiguous floats), coalesced ----
    const float* Wg = W + ((size_t)o * Iz + i0) * 256;
    for (int idx = tid; idx < 8192; idx += 256) {
        int ils = idx >> 8, j = idx & 255;
        pool[ils * 264 + j] = Wg[idx];
    }
    __syncthreads();

    // ---- pull this thread's 2 W rows into registers ----
    float wA[16], wB[16];
    {
        const float* r0 = &pool[il * 264 + (2 * dg) * 16];
        const float* r1 = r0 + 16;
        #pragma unroll
        for (int q = 0; q < 4; q++) {
            float4 a = *(const float4*)(r0 + q * 4);
            float4 b = *(const float4*)(r1 + q * 4);
            wA[q*4+0] = a.x; wA[q*4+1] = a.y; wA[q*4+2] = a.z; wA[q*4+3] = a.w;
            wB[q*4+0] = b.x; wB[q*4+1] = b.y; wB[q*4+2] = b.z; wB[q*4+3] = b.w;
        }
    }
    __syncthreads();   // everyone done reading W before u overwrites pool

    // ---- 4 chunks of 16 batches ----
    for (int bc = 0; bc < 4; bc++) {
        // stage u[bc*16 .. bc*16+15][i0..i0+31][:] : 16 x 512 contiguous floats
        const float* ug = u + ((size_t)(bc * 16) * Iz + i0) * 16;
        for (int idx = tid; idx < 8192; idx += 256) {
            int bl = idx >> 9, r = idx & 511;
            pool[bl * 512 + r] = ug[(size_t)bl * Iz * 16 + r];
        }
        // stage ||u|| for this chunk (512 entries, 256 threads -> 2 per thread)
        for (int idx = tid; idx < 512; idx += 256) {
            int bl = idx >> 5, ii = idx & 31;
            un_sm[idx] = g_unorm[(size_t)(bc * 16 + bl) * Iz + i0 + ii];
        }
        __syncthreads();

        #pragma unroll 4
        for (int bl = 0; bl < 16; bl++) {
            const float* ub = &pool[bl * 512 + il * 16];   // broadcast reads
            float4 u0 = *(const float4*)(ub + 0);
            float4 u1 = *(const float4*)(ub + 4);
            float4 u2 = *(const float4*)(ub + 8);
            float4 u3 = *(const float4*)(ub + 12);
            float uu[16] = {u0.x,u0.y,u0.z,u0.w, u1.x,u1.y,u1.z,u1.w,
                            u2.x,u2.y,u2.z,u2.w, u3.x,u3.y,u3.z,u3.w};

            float a0 = 0.f, a1 = 0.f;
            #pragma unroll
            for (int k = 0; k < 16; k++) {
                a0 += wA[k] * uu[k];
                a1 += wB[k] * uu[k];
            }

            // ||u_hat||^2 over all 16 d: reduce across the 8 dg lanes
            float n2 = a0 * a0 + a1 * a1;
            n2 += __shfl_xor_sync(0xffffffffu, n2, 1);
            n2 += __shfl_xor_sync(0xffffffffu, n2, 2);
            n2 += __shfl_xor_sync(0xffffffffu, n2, 4);

            float nh = sqrtf(n2);
            float nu = un_sm[bl * 32 + il];
            float sc = fminf(nh, nu) / (nh + 1e-12f);

            const int b = bc * 16 + bl;
            // [b][o][i][d] layout: adjacent d pair -> one float2 store
            float2* dst = (float2*)(g_uhat + ((size_t)(b * Oz + o) * Iz + i) * Dz + 2 * dg);
            *dst = make_float2(a0 * sc, a1 * sc);
        }
        __syncthreads();   // before next chunk overwrites pool
    }
}

// =======================================================================
// k_sd: FUSED s/v + distance. Phase 1 reads u_hat from DRAM, phase 2
// re-reads it from L2 (slab is 128 KiB, just touched).
//   mode 0: c = 1/O uniform ; mode 1: c = g_c.
// Grid: (O, B). Block: 512; thread t owns i = t + 512*jj (jj=0..3),
// reading 16 contiguous d floats per i (4x LDG.128, coalesced per warp).
// =======================================================================
__global__ __launch_bounds__(512, 2) void k_sd(int mode, const float* __restrict__ bias)
{
    const int o = blockIdx.x;
    const int b = blockIdx.y;
    const size_t base = (size_t)(b * Oz + o);
    const float* uh = g_uhat + base * Iz * Dz;
    const float* cp = g_c + base * Iz;
    const int t = threadIdx.x;

    // ---- phase 1: s accumulation ----
    float acc[16];
    #pragma unroll
    for (int d = 0; d < 16; d++) acc[d] = 0.f;

    #pragma unroll
    for (int jj = 0; jj < 4; jj++) {
        const int i = t + jj * 512;
        const float cc = (mode == 0) ? (1.0f / 32.0f) : cp[i];
        const float4* p = (const float4*)(uh + (size_t)i * Dz);
        #pragma unroll
        for (int q = 0; q < 4; q++) {
            float4 x = p[q];
            acc[q*4+0] += cc * x.x;
            acc[q*4+1] += cc * x.y;
            acc[q*4+2] += cc * x.z;
            acc[q*4+3] += cc * x.w;
        }
    }

    // reduce across 512 threads (16 warps)
    #pragma unroll
    for (int d = 0; d < 16; d++) {
        #pragma unroll
        for (int off = 16; off > 0; off >>= 1)
            acc[d] += __shfl_down_sync(0xffffffffu, acc[d], off);
    }

    __shared__ float red[16][16];
    __shared__ float vsm[16];
    const int lane = t & 31;
    const int wid  = t >> 5;
    if (lane == 0) {
        #pragma unroll
        for (int d = 0; d < 16; d++) red[wid][d] = acc[d];
    }
    __syncthreads();

    if (t < 16) {
        const int d = t;
        float tot = 0.f;
        #pragma unroll
        for (int w = 0; w < 16; w++) tot += red[w][d];
        float s = tot + bias[o * Dz + d];

        float n2 = s * s;
        #pragma unroll
        for (int off = 8; off > 0; off >>= 1)
            n2 += __shfl_xor_sync(0x0000ffffu, n2, off);

        vsm[d] = s * (n2 / ((1.0f + n2) * sqrtf(n2 + 1e-12f)));
    }
    __syncthreads();

    // ---- phase 2: distances (u_hat re-read hits L2) ----
    float vr[16];
    #pragma unroll
    for (int d = 0; d < 16; d++) vr[d] = vsm[d];

    float* dp = g_d + base * Iz;
    float lsum = 0.f;
    #pragma unroll
    for (int jj = 0; jj < 4; jj++) {
        const int i = t + jj * 512;
        const float4* p = (const float4*)(uh + (size_t)i * Dz);
        float s2 = 0.f;
        #pragma unroll
        for (int q = 0; q < 4; q++) {
            float4 x = p[q];
            float d0 = vr[q*4+0] - x.x;
            float d1 = vr[q*4+1] - x.y;
            float d2 = vr[q*4+2] - x.z;
            float d3 = vr[q*4+3] - x.w;
            s2 += d0*d0 + d1*d1 + d2*d2 + d3*d3;
        }
        float dd = sqrtf(s2);
        dp[i] = dd;
        lsum += dd;
    }

    #pragma unroll
    for (int off = 16; off > 0; off >>= 1)
        lsum += __shfl_down_sync(0xffffffffu, lsum, off);

    __shared__ float red1[16];
    if (lane == 0) red1[wid] = lsum;
    __syncthreads();
    if (t == 0) {
        float tt = 0.f;
        #pragma unroll
        for (int w = 0; w < 16; w++) tt += red1[w];
        g_partial[base] = tt;
    }
}

// =======================================================================
// k_c: computes t from g_partial (deterministic fixed-order, identical in
// every block), then c[b,o,i] = softmax over o of (t * d[b,o,i]).
// cout == nullptr -> write g_c, else write cout (final output region).
// =======================================================================
__global__ __launch_bounds__(256, 1) void k_c(float* __restrict__ cout)
{
    __shared__ float psum[256];
    __shared__ float tsh;
    {
        float s = 0.f;
        const int j0 = threadIdx.x * 8;
        #pragma unroll
        for (int j = 0; j < 8; j++) s += g_partial[j0 + j];
        psum[threadIdx.x] = s;
    }
    __syncthreads();
    if (threadIdx.x == 0) {
        float tot = 0.f;
        for (int w = 0; w < 256; w++) tot += psum[w];
        float mean = tot / (float)((size_t)Bz * Oz * Iz);
        const float t_const = 5.6312118f;   // ln(279)
        tsh = t_const / (1e-12f - 0.5f * mean);
    }
    __syncthreads();
    const float t = tsh;

    const int idx = blockIdx.x * 256 + threadIdx.x;
    const int b = idx >> 11;
    const int i = idx & (Iz - 1);

    float vals[32];
    float mx = -1e30f;
    #pragma unroll
    for (int o = 0; o < 32; o++) {
        float x = t * g_d[(size_t)(b * Oz + o) * Iz + i];
        vals[o] = x;
        mx = fmaxf(mx, x);
    }
    float ssum = 0.f;
    #pragma unroll
    for (int o = 0; o < 32; o++) {
        float e = expf(vals[o] - mx);
        vals[o] = e;
        ssum += e;
    }
    float inv = 1.0f / ssum;
    float* dst = cout ? cout : g_c;
    #pragma unroll
    for (int o = 0; o < 32; o++)
        dst[(size_t)(b * Oz + o) * Iz + i] = vals[o] * inv;
}

// =======================================================================
// k_s_final: final s/v with c read from the output buffer; writes v to out.
// Grid: (O, B). Block: 512; same load structure as k_sd phase 1.
// =======================================================================
__global__ __launch_bounds__(512, 2) void k_s_final(const float* __restrict__ cext,
                                                    const float* __restrict__ bias,
                                                    float* __restrict__ vext)
{
    const int o = blockIdx.x;
    const int b = blockIdx.y;
    const size_t base = (size_t)(b * Oz + o);
    const float* uh = g_uhat + base * Iz * Dz;
    const float* cp = cext + base * Iz;
    const int t = threadIdx.x;

    float acc[16];
    #pragma unroll
    for (int d = 0; d < 16; d++) acc[d] = 0.f;

    #pragma unroll
    for (int jj = 0; jj < 4; jj++) {
        const int i = t + jj * 512;
        const float cc = cp[i];
        const float4* p = (const float4*)(uh + (size_t)i * Dz);
        #pragma unroll
        for (int q = 0; q < 4; q++) {
            float4 x = p[q];
            acc[q*4+0] += cc * x.x;
            acc[q*4+1] += cc * x.y;
            acc[q*4+2] += cc * x.z;
            acc[q*4+3] += cc * x.w;
        }
    }

    #pragma unroll
    for (int d = 0; d < 16; d++) {
        #pragma unroll
        for (int off = 16; off > 0; off >>= 1)
            acc[d] += __shfl_down_sync(0xffffffffu, acc[d], off);
    }

    __shared__ float red[16][16];
    const int lane = t & 31;
    const int wid  = t >> 5;
    if (lane == 0) {
        #pragma unroll
        for (int d = 0; d < 16; d++) red[wid][d] = acc[d];
    }
    __syncthreads();

    if (t < 16) {
        const int d = t;
        float tot = 0.f;
        #pragma unroll
        for (int w = 0; w < 16; w++) tot += red[w][d];
        float s = tot + bias[o * Dz + d];

        float n2 = s * s;
        #pragma unroll
        for (int off = 8; off > 0; off >>= 1)
            n2 += __shfl_xor_sync(0x0000ffffu, n2, off);

        vext[(b * Oz + o) * Dz + d] = s * (n2 / ((1.0f + n2) * sqrtf(n2 + 1e-12f)));
    }
}

// =======================================================================
extern "C" void kernel_launch(void* const* d_in, const int* in_sizes, int n_in,
                              void* d_out, int out_size)
{
    const float* u    = (const float*)d_in[0];   // [64, 2048, 16]
    const float* W    = (const float*)d_in[1];   // [1, 32, 2048, 16, 16]
    const float* bias = (const float*)d_in[2];   // [1, 32, 16]

    float* out        = (float*)d_out;
    float* vout_final = out;                     // [64,32,16]
    float* cout_final = out + Bz * Oz * Dz;      // [64,32,2048,1]

    dim3 gUH(Iz / 32, Oz);
    dim3 gBO(Oz, Bz);

    k_unorm<<<(Bz * Iz) / 256, 256>>>(u);
    k_uhat<<<gUH, 256>>>(u, W);

    // iteration 0: c uniform; fused s/v + d
    k_sd<<<gBO, 512>>>(0, bias);

    // iteration 1
    k_c<<<(Bz * Iz) / 256, 256>>>(nullptr);      // t + softmax -> g_c
    k_sd<<<gBO, 512>>>(1, bias);

    // iteration 2 (final): c2 and v2 go straight to d_out
    k_c<<<(Bz * Iz) / 256, 256>>>(cout_final);   // t + softmax -> out
    k_s_final<<<gBO, 512>>>(cout_final, bias, vout_final);
}

// round 12
// speedup vs baseline: 1.2063x; 1.2063x over previous
#include <cuda_runtime.h>
#include <math.h>

// Problem constants
#define Bz 64
#define Oz 32
#define Iz 2048
#define Dz 16   // DOUT == DIN == 16

// ---------------- scratch (static device globals; no allocation) ----------------
// u_hat layout: [b][o][d][i]  (i contiguous -> perfectly coalesced reads in the
// 5 reader passes; k_uhat stores fixed via smem transpose staging)
__device__ float g_uhat[(size_t)Bz * Oz * Dz * Iz];   // 256 MiB
__device__ float g_d[(size_t)Bz * Oz * Iz];           // distances d[b][o][i]
__device__ float g_c[(size_t)Bz * Oz * Iz];           // routing coeffs (iter-1 scratch)
__device__ float g_partial[Bz * Oz];                  // per-CTA partial sums of d
__device__ float g_unorm[(size_t)Bz * Iz];            // ||u[b,i]|| (precomputed)

// =======================================================================
// k_unorm: ||u[b,i]|| for all (b,i). 128K threads, trivially coalesced.
// =======================================================================
__global__ __launch_bounds__(256) void k_unorm(const float* __restrict__ u)
{
    const int idx = blockIdx.x * 256 + threadIdx.x;   // b*Iz + i
    const float4* up = (const float4*)(u + (size_t)idx * 16);
    float n2 = 0.f;
    #pragma unroll
    for (int q = 0; q < 4; q++) {
        float4 t = up[q];
        n2 += t.x*t.x + t.y*t.y + t.z*t.z + t.w*t.w;
    }
    g_unorm[idx] = sqrtf(n2);
}

// =======================================================================
// K1: u_hat[b,o,d,i] = clip( sum_k W[o,i,d,k] * u[b,i,k] )
// Grid: (I/32, O). Block: 256 = 8 warps; lane = il_local*8 + dg.
// W rows for this thread's 2 d's live in REGISTERS. u staged in smem.
// Norm over d via 3 shfl_xor in the 8-lane dg group (all in-warp).
// STORES: results for groups of 4 batches staged to smem [i][d] (stride 18),
// then re-read transposed so each 16-lane half-warp writes one contiguous
// 128B d-row run -> 2 wavefronts per STG.64 instead of 8 per STG.32.
// =======================================================================
#define SSTR 18                 // stage stride per i (even -> aligned float2 STS)
__global__ __launch_bounds__(256) void k_uhat(const float* __restrict__ u,
                                              const float* __restrict__ W)
{
    __shared__ float pool[32 * 264];        // 33.8 KB: W staging, then u chunks
    __shared__ float un_sm[512];            // ||u|| for current chunk
    __shared__ float stage[4 * 32 * SSTR];  // 9.2 KB: 4 batches x 32 i x 16 d

    const int o  = blockIdx.y;
    const int i0 = blockIdx.x * 32;
    const int tid  = threadIdx.x;
    const int w    = tid >> 5;
    const int lane = tid & 31;
    const int il_l = lane >> 3;             // 0..3
    const int dg   = lane & 7;              // 0..7 -> d rows 2dg, 2dg+1
    const int il   = w * 4 + il_l;          // 0..31
    const int dd   = tid >> 4;              // store phase: d row 0..15
    const int ip   = tid & 15;              // store phase: i pair 0..15

    // ---- stage W[o, i0..i0+31, :, :] (8192 contiguous floats), coalesced ----
    const float* Wg = W + ((size_t)o * Iz + i0) * 256;
    for (int idx = tid; idx < 8192; idx += 256) {
        int ils = idx >> 8, j = idx & 255;
        pool[ils * 264 + j] = Wg[idx];
    }
    __syncthreads();

    // ---- pull this thread's 2 W rows into registers ----
    float wA[16], wB[16];
    {
        const float* r0 = &pool[il * 264 + (2 * dg) * 16];
        const float* r1 = r0 + 16;
        #pragma unroll
        for (int q = 0; q < 4; q++) {
            float4 a = *(const float4*)(r0 + q * 4);
            float4 b = *(const float4*)(r1 + q * 4);
            wA[q*4+0] = a.x; wA[q*4+1] = a.y; wA[q*4+2] = a.z; wA[q*4+3] = a.w;
            wB[q*4+0] = b.x; wB[q*4+1] = b.y; wB[q*4+2] = b.z; wB[q*4+3] = b.w;
        }
    }
    __syncthreads();   // everyone done reading W before u overwrites pool

    // ---- 4 chunks of 16 batches ----
    for (int bc = 0; bc < 4; bc++) {
        // stage u[bc*16 .. +15][i0..i0+31][:] : 16 x 512 contiguous floats
        const float* ug = u + ((size_t)(bc * 16) * Iz + i0) * 16;
        for (int idx = tid; idx < 8192; idx += 256) {
            int bl = idx >> 9, r = idx & 511;
            pool[bl * 512 + r] = ug[(size_t)bl * Iz * 16 + r];
        }
        for (int idx = tid; idx < 512; idx += 256) {
            int bl = idx >> 5, ii = idx & 31;
            un_sm[idx] = g_unorm[(size_t)(bc * 16 + bl) * Iz + i0 + ii];
        }
        __syncthreads();

        for (int bg4 = 0; bg4 < 4; bg4++) {
            // ---- compute 4 batches into stage ----
            #pragma unroll
            for (int blq = 0; blq < 4; blq++) {
                const int bl = bg4 * 4 + blq;
                const float* ub = &pool[bl * 512 + il * 16];   // 8-lane broadcast
                float4 u0 = *(const float4*)(ub + 0);
                float4 u1 = *(const float4*)(ub + 4);
                float4 u2 = *(const float4*)(ub + 8);
                float4 u3 = *(const float4*)(ub + 12);
                float uu[16] = {u0.x,u0.y,u0.z,u0.w, u1.x,u1.y,u1.z,u1.w,
                                u2.x,u2.y,u2.z,u2.w, u3.x,u3.y,u3.z,u3.w};

                float a0 = 0.f, a1 = 0.f;
                #pragma unroll
                for (int k = 0; k < 16; k++) {
                    a0 += wA[k] * uu[k];
                    a1 += wB[k] * uu[k];
                }

                float n2 = a0 * a0 + a1 * a1;
                n2 += __shfl_xor_sync(0xffffffffu, n2, 1);
                n2 += __shfl_xor_sync(0xffffffffu, n2, 2);
                n2 += __shfl_xor_sync(0xffffffffu, n2, 4);

                float nh = sqrtf(n2);
                float nu = un_sm[bl * 32 + il];
                float sc = fminf(nh, nu) / (nh + 1e-12f);

                *(float2*)&stage[(blq * 32 + il) * SSTR + 2 * dg] =
                    make_float2(a0 * sc, a1 * sc);
            }
            __syncthreads();

            // ---- coalesced store: 16-lane group writes contiguous 128B run ----
            #pragma unroll
            for (int blq = 0; blq < 4; blq++) {
                const int b = bc * 16 + bg4 * 4 + blq;
                float v0 = stage[(blq * 32 + 2 * ip)     * SSTR + dd];
                float v1 = stage[(blq * 32 + 2 * ip + 1) * SSTR + dd];
                *(float2*)(g_uhat + (size_t)(b * Oz + o) * Dz * Iz
                           + (size_t)dd * Iz + i0 + 2 * ip) = make_float2(v0, v1);
            }
            __syncthreads();   // before next group's STS overwrites stage
        }
    }
}

// =======================================================================
// k_sd: FUSED s/v + distance. Phase 1 reads u_hat from DRAM, phase 2
// re-reads it from L2 (slab is 128 KiB, just touched). Low regs, float4.
//   mode 0: c = 1/O uniform ; mode 1: c = g_c.
// Grid: (O, B). Block: 512 (each thread owns 4 consecutive i via float4).
// =======================================================================
__global__ __launch_bounds__(512, 2) void k_sd(int mode, const float* __restrict__ bias)
{
    const int o = blockIdx.x;
    const int b = blockIdx.y;
    const size_t base = (size_t)(b * Oz + o);
    const float4* uh4 = (const float4*)(g_uhat + base * Dz * Iz);
    const int t = threadIdx.x;

    // ---- phase 1: s accumulation ----
    float4 cc;
    if (mode == 0) cc = make_float4(1.f/32.f, 1.f/32.f, 1.f/32.f, 1.f/32.f);
    else           cc = ((const float4*)(g_c + base * Iz))[t];

    float acc[16];
    #pragma unroll
    for (int d = 0; d < 16; d++) {
        float4 x = uh4[d * 512 + t];
        acc[d] = cc.x*x.x + cc.y*x.y + cc.z*x.z + cc.w*x.w;
    }

    // reduce across 512 threads (16 warps)
    #pragma unroll
    for (int d = 0; d < 16; d++) {
        #pragma unroll
        for (int off = 16; off > 0; off >>= 1)
            acc[d] += __shfl_down_sync(0xffffffffu, acc[d], off);
    }

    __shared__ float red[16][16];
    __shared__ float vsm[16];
    const int lane = t & 31;
    const int wid  = t >> 5;
    if (lane == 0) {
        #pragma unroll
        for (int d = 0; d < 16; d++) red[wid][d] = acc[d];
    }
    __syncthreads();

    if (t < 16) {
        const int d = t;
        float tot = 0.f;
        #pragma unroll
        for (int w = 0; w < 16; w++) tot += red[w][d];
        float s = tot + bias[o * Dz + d];

        float n2 = s * s;
        #pragma unroll
        for (int off = 8; off > 0; off >>= 1)
            n2 += __shfl_xor_sync(0x0000ffffu, n2, off);

        vsm[d] = s * (n2 / ((1.0f + n2) * sqrtf(n2 + 1e-12f)));
    }
    __syncthreads();

    // ---- phase 2: distances (u_hat re-read hits L2) ----
    float4 s2 = make_float4(0.f, 0.f, 0.f, 0.f);
    #pragma unroll
    for (int d = 0; d < 16; d++) {
        float vd = vsm[d];
        float4 x = uh4[d * 512 + t];
        float dx = vd - x.x, dy = vd - x.y, dz = vd - x.z, dw = vd - x.w;
        s2.x += dx*dx; s2.y += dy*dy; s2.z += dz*dz; s2.w += dw*dw;
    }
    float4 dd = make_float4(sqrtf(s2.x), sqrtf(s2.y), sqrtf(s2.z), sqrtf(s2.w));
    ((float4*)(g_d + base * Iz))[t] = dd;

    float lsum = (dd.x + dd.y) + (dd.z + dd.w);
    #pragma unroll
    for (int off = 16; off > 0; off >>= 1)
        lsum += __shfl_down_sync(0xffffffffu, lsum, off);

    __shared__ float red1[16];
    if (lane == 0) red1[wid] = lsum;
    __syncthreads();
    if (t == 0) {
        float tt = 0.f;
        #pragma unroll
        for (int w = 0; w < 16; w++) tt += red1[w];
        g_partial[base] = tt;
    }
}

// =======================================================================
// k_c: computes t from g_partial (deterministic fixed-order, identical in
// every block), then c[b,o,i] = softmax over o of (t * d[b,o,i]).
// cout == nullptr -> write g_c, else write cout (final output region).
// =======================================================================
__global__ __launch_bounds__(256, 1) void k_c(float* __restrict__ cout)
{
    __shared__ float psum[256];
    __shared__ float tsh;
    {
        float s = 0.f;
        const int j0 = threadIdx.x * 8;
        #pragma unroll
        for (int j = 0; j < 8; j++) s += g_partial[j0 + j];
        psum[threadIdx.x] = s;
    }
    __syncthreads();
    if (threadIdx.x == 0) {
        float tot = 0.f;
        for (int w = 0; w < 256; w++) tot += psum[w];
        float mean = tot / (float)((size_t)Bz * Oz * Iz);
        const float t_const = 5.6312118f;   // ln(279)
        tsh = t_const / (1e-12f - 0.5f * mean);
    }
    __syncthreads();
    const float t = tsh;

    const int idx = blockIdx.x * 256 + threadIdx.x;
    const int b = idx >> 11;
    const int i = idx & (Iz - 1);

    float vals[32];
    float mx = -1e30f;
    #pragma unroll
    for (int o = 0; o < 32; o++) {
        float x = t * g_d[(size_t)(b * Oz + o) * Iz + i];
        vals[o] = x;
        mx = fmaxf(mx, x);
    }
    float ssum = 0.f;
    #pragma unroll
    for (int o = 0; o < 32; o++) {
        float e = expf(vals[o] - mx);
        vals[o] = e;
        ssum += e;
    }
    float inv = 1.0f / ssum;
    float* dst = cout ? cout : g_c;
    #pragma unroll
    for (int o = 0; o < 32; o++)
        dst[(size_t)(b * Oz + o) * Iz + i] = vals[o] * inv;
}

// =======================================================================
// k_s_final: final s/v with c read from the output buffer; writes v to out.
// Grid: (O, B). Block: 512, float4 over i.
// =======================================================================
__global__ __launch_bounds__(512, 2) void k_s_final(const float* __restrict__ cext,
                                                    const float* __restrict__ bias,
                                                    float* __restrict__ vext)
{
    const int o = blockIdx.x;
    const int b = blockIdx.y;
    const size_t base = (size_t)(b * Oz + o);
    const float4* uh4 = (const float4*)(g_uhat + base * Dz * Iz);
    const int t = threadIdx.x;

    float4 cc = ((const float4*)(cext + base * Iz))[t];

    float acc[16];
    #pragma unroll
    for (int d = 0; d < 16; d++) {
        float4 x = uh4[d * 512 + t];
        acc[d] = cc.x*x.x + cc.y*x.y + cc.z*x.z + cc.w*x.w;
    }

    #pragma unroll
    for (int d = 0; d < 16; d++) {
        #pragma unroll
        for (int off = 16; off > 0; off >>= 1)
            acc[d] += __shfl_down_sync(0xffffffffu, acc[d], off);
    }

    __shared__ float red[16][16];
    const int lane = t & 31;
    const int wid  = t >> 5;
    if (lane == 0) {
        #pragma unroll
        for (int d = 0; d < 16; d++) red[wid][d] = acc[d];
    }
    __syncthreads();

    if (t < 16) {
        const int d = t;
        float tot = 0.f;
        #pragma unroll
        for (int w = 0; w < 16; w++) tot += red[w][d];
        float s = tot + bias[o * Dz + d];

        float n2 = s * s;
        #pragma unroll
        for (int off = 8; off > 0; off >>= 1)
            n2 += __shfl_xor_sync(0x0000ffffu, n2, off);

        vext[(b * Oz + o) * Dz + d] = s * (n2 / ((1.0f + n2) * sqrtf(n2 + 1e-12f)));
    }
}

// =======================================================================
extern "C" void kernel_launch(void* const* d_in, const int* in_sizes, int n_in,
                              void* d_out, int out_size)
{
    const float* u    = (const float*)d_in[0];   // [64, 2048, 16]
    const float* W    = (const float*)d_in[1];   // [1, 32, 2048, 16, 16]
    const float* bias = (const float*)d_in[2];   // [1, 32, 16]

    float* out        = (float*)d_out;
    float* vout_final = out;                     // [64,32,16]
    float* cout_final = out + Bz * Oz * Dz;      // [64,32,2048,1]

    dim3 gUH(Iz / 32, Oz);
    dim3 gBO(Oz, Bz);

    k_unorm<<<(Bz * Iz) / 256, 256>>>(u);
    k_uhat<<<gUH, 256>>>(u, W);

    // iteration 0: c uniform; fused s/v + d
    k_sd<<<gBO, 512>>>(0, bias);

    // iteration 1
    k_c<<<(Bz * Iz) / 256, 256>>>(nullptr);      // t + softmax -> g_c
    k_sd<<<gBO, 512>>>(1, bias);

    // iteration 2 (final): c2 and v2 go straight to d_out
    k_c<<<(Bz * Iz) / 256, 256>>>(cout_final);   // t + softmax -> out
    k_s_final<<<gBO, 512>>>(cout_final, bias, vout_final);
}

// round 13
// speedup vs baseline: 1.4535x; 1.2048x over previous
#include <cuda_runtime.h>
#include <math.h>

// Problem constants
#define Bz 64
#define Oz 32
#define Iz 2048
#define Dz 16   // DOUT == DIN == 16

// ---------------- scratch (static device globals; no allocation) ----------------
// u_hat layout: [b][o][dg][i][2]  with dg = d/2 (8 rows of 2*Iz floats per (b,o)).
// Writer: one STG.64 per (i, d-pair) -> full 32B sectors.
// Readers: float4 = (d0,d1) x (i, i+1), lanes contiguous -> fully coalesced.
__device__ float g_uhat[(size_t)Bz * Oz * Dz * Iz];   // 256 MiB
__device__ float g_d[(size_t)Bz * Oz * Iz];           // distances d[b][o][i]
__device__ float g_c[(size_t)Bz * Oz * Iz];           // routing coeffs (iter-1 scratch)
__device__ float g_partial[Bz * Oz];                  // per-CTA partial sums of d
__device__ float g_unorm[(size_t)Bz * Iz];            // ||u[b,i]|| (precomputed)

// =======================================================================
// k_unorm: ||u[b,i]|| for all (b,i). 128K threads, trivially coalesced.
// =======================================================================
__global__ __launch_bounds__(256) void k_unorm(const float* __restrict__ u)
{
    const int idx = blockIdx.x * 256 + threadIdx.x;   // b*Iz + i
    const float4* up = (const float4*)(u + (size_t)idx * 16);
    float n2 = 0.f;
    #pragma unroll
    for (int q = 0; q < 4; q++) {
        float4 t = up[q];
        n2 += t.x*t.x + t.y*t.y + t.z*t.z + t.w*t.w;
    }
    g_unorm[idx] = sqrtf(n2);
}

// =======================================================================
// K1: u_hat[b,o,dg,i,{0,1}] = clip( sum_k W[o,i,d,k] * u[b,i,k] )
// Grid: (I/32, O). Block: 256 = 8 warps; lane = il_local*8 + dg.
//   warp w covers i = i0 + 4w .. 4w+3 (il_local 0..3), dg = d-pair 0..7.
// W rows for this thread's 2 d's live in REGISTERS (32 floats, loaded once).
// u staged to smem in 16-batch chunks; inner LDS.128 are 8-lane broadcasts.
// Norm over d reduced with 3 shfl_xor inside the 8-lane dg group.
// Store: adjacent d-pair -> ONE STG.64 per (i,bl); each touched 32B sector full.
// =======================================================================
__global__ __launch_bounds__(256) void k_uhat(const float* __restrict__ u,
                                              const float* __restrict__ W)
{
    __shared__ float pool[32 * 264];        // 33.8 KB: W staging, then u chunks
    __shared__ float un_sm[512];            // ||u|| for current chunk (16b x 32i)

    const int o  = blockIdx.y;
    const int i0 = blockIdx.x * 32;
    const int tid  = threadIdx.x;
    const int w    = tid >> 5;
    const int lane = tid & 31;
    const int il_l = lane >> 3;             // 0..3
    const int dg   = lane & 7;              // 0..7 -> d rows 2dg, 2dg+1
    const int il   = w * 4 + il_l;          // 0..31
    const int i    = i0 + il;

    // ---- stage W[o, i0..i0+31, :, :] (8192 contiguous floats), coalesced ----
    const float* Wg = W + ((size_t)o * Iz + i0) * 256;
    for (int idx = tid; idx < 8192; idx += 256) {
        int ils = idx >> 8, j = idx & 255;
        pool[ils * 264 + j] = Wg[idx];
    }
    __syncthreads();

    // ---- pull this thread's 2 W rows into registers ----
    float wA[16], wB[16];
    {
        const float* r0 = &pool[il * 264 + (2 * dg) * 16];
        const float* r1 = r0 + 16;
        #pragma unroll
        for (int q = 0; q < 4; q++) {
            float4 a = *(const float4*)(r0 + q * 4);
            float4 b = *(const float4*)(r1 + q * 4);
            wA[q*4+0] = a.x; wA[q*4+1] = a.y; wA[q*4+2] = a.z; wA[q*4+3] = a.w;
            wB[q*4+0] = b.x; wB[q*4+1] = b.y; wB[q*4+2] = b.z; wB[q*4+3] = b.w;
        }
    }
    __syncthreads();   // everyone done reading W before u overwrites pool

    // ---- 4 chunks of 16 batches ----
    for (int bc = 0; bc < 4; bc++) {
        // stage u[bc*16 .. bc*16+15][i0..i0+31][:] : 16 x 512 contiguous floats
        const float* ug = u + ((size_t)(bc * 16) * Iz + i0) * 16;
        for (int idx = tid; idx < 8192; idx += 256) {
            int bl = idx >> 9, r = idx & 511;
            pool[bl * 512 + r] = ug[(size_t)bl * Iz * 16 + r];
        }
        // stage ||u|| for this chunk (512 entries, 256 threads -> 2 per thread)
        for (int idx = tid; idx < 512; idx += 256) {
            int bl = idx >> 5, ii = idx & 31;
            un_sm[idx] = g_unorm[(size_t)(bc * 16 + bl) * Iz + i0 + ii];
        }
        __syncthreads();

        #pragma unroll 4
        for (int bl = 0; bl < 16; bl++) {
            const float* ub = &pool[bl * 512 + il * 16];   // broadcast reads
            float4 u0 = *(const float4*)(ub + 0);
            float4 u1 = *(const float4*)(ub + 4);
            float4 u2 = *(const float4*)(ub + 8);
            float4 u3 = *(const float4*)(ub + 12);
            float uu[16] = {u0.x,u0.y,u0.z,u0.w, u1.x,u1.y,u1.z,u1.w,
                            u2.x,u2.y,u2.z,u2.w, u3.x,u3.y,u3.z,u3.w};

            float a0 = 0.f, a1 = 0.f;
            #pragma unroll
            for (int k = 0; k < 16; k++) {
                a0 += wA[k] * uu[k];
                a1 += wB[k] * uu[k];
            }

            // ||u_hat||^2 over all 16 d: reduce across the 8 dg lanes
            float n2 = a0 * a0 + a1 * a1;
            n2 += __shfl_xor_sync(0xffffffffu, n2, 1);
            n2 += __shfl_xor_sync(0xffffffffu, n2, 2);
            n2 += __shfl_xor_sync(0xffffffffu, n2, 4);

            float nh = sqrtf(n2);
            float nu = un_sm[bl * 32 + il];
            float sc = fminf(nh, nu) / (nh + 1e-12f);

            const int b = bc * 16 + bl;
            // pair-interleaved: one STG.64 to row dg at column i
            float2* dst = (float2*)(g_uhat + (size_t)(b * Oz + o) * Dz * Iz
                                    + (size_t)dg * 2 * Iz) + i;
            *dst = make_float2(a0 * sc, a1 * sc);
        }
        __syncthreads();   // before next chunk overwrites pool
    }
}

// =======================================================================
// k_sd: FUSED s/v + distance. Phase 1 reads u_hat from DRAM, phase 2
// re-reads it from L2 (slab is 128 KiB, just touched).
//   mode 0: c = 1/O uniform ; mode 1: c = g_c.
// Grid: (O, B). Block: 512. Thread t handles float4 columns j = t, t+512
// of the 8 dg-rows (each float4 = (d0,d1)x(i=2j, 2j+1)).
// =======================================================================
__global__ __launch_bounds__(512, 2) void k_sd(int mode, const float* __restrict__ bias)
{
    const int o = blockIdx.x;
    const int b = blockIdx.y;
    const size_t base = (size_t)(b * Oz + o);
    const float4* uh4 = (const float4*)(g_uhat + base * Dz * Iz);  // rows of 1024 float4
    const float2* cp2 = (const float2*)(g_c + base * Iz);
    const int t = threadIdx.x;

    // ---- phase 1: s accumulation ----
    float acc[16];
    #pragma unroll
    for (int d = 0; d < 16; d++) acc[d] = 0.f;

    #pragma unroll
    for (int jj = 0; jj < 2; jj++) {
        const int j = t + jj * 512;
        float2 cc = (mode == 0) ? make_float2(1.f/32.f, 1.f/32.f) : cp2[j];
        #pragma unroll
        for (int dg = 0; dg < 8; dg++) {
            float4 x = uh4[dg * 1024 + j];
            acc[2*dg+0] += cc.x * x.x + cc.y * x.z;
            acc[2*dg+1] += cc.x * x.y + cc.y * x.w;
        }
    }

    // reduce across 512 threads (16 warps)
    #pragma unroll
    for (int d = 0; d < 16; d++) {
        #pragma unroll
        for (int off = 16; off > 0; off >>= 1)
            acc[d] += __shfl_down_sync(0xffffffffu, acc[d], off);
    }

    __shared__ float red[16][16];
    __shared__ float vsm[16];
    const int lane = t & 31;
    const int wid  = t >> 5;
    if (lane == 0) {
        #pragma unroll
        for (int d = 0; d < 16; d++) red[wid][d] = acc[d];
    }
    __syncthreads();

    if (t < 16) {
        const int d = t;
        float tot = 0.f;
        #pragma unroll
        for (int w = 0; w < 16; w++) tot += red[w][d];
        float s = tot + bias[o * Dz + d];

        float n2 = s * s;
        #pragma unroll
        for (int off = 8; off > 0; off >>= 1)
            n2 += __shfl_xor_sync(0x0000ffffu, n2, off);

        vsm[d] = s * (n2 / ((1.0f + n2) * sqrtf(n2 + 1e-12f)));
    }
    __syncthreads();

    // ---- phase 2: distances (u_hat re-read hits L2) ----
    float vr[16];
    #pragma unroll
    for (int d = 0; d < 16; d++) vr[d] = vsm[d];

    float2* dp2 = (float2*)(g_d + base * Iz);
    float lsum = 0.f;
    #pragma unroll
    for (int jj = 0; jj < 2; jj++) {
        const int j = t + jj * 512;
        float s2a = 0.f, s2b = 0.f;
        #pragma unroll
        for (int dg = 0; dg < 8; dg++) {
            float4 x = uh4[dg * 1024 + j];
            float e0 = vr[2*dg+0] - x.x;
            float e1 = vr[2*dg+1] - x.y;
            float e2 = vr[2*dg+0] - x.z;
            float e3 = vr[2*dg+1] - x.w;
            s2a += e0*e0 + e1*e1;
            s2b += e2*e2 + e3*e3;
        }
        float da = sqrtf(s2a), db = sqrtf(s2b);
        dp2[j] = make_float2(da, db);
        lsum += da + db;
    }

    #pragma unroll
    for (int off = 16; off > 0; off >>= 1)
        lsum += __shfl_down_sync(0xffffffffu, lsum, off);

    __shared__ float red1[16];
    if (lane == 0) red1[wid] = lsum;
    __syncthreads();
    if (t == 0) {
        float tt = 0.f;
        #pragma unroll
        for (int w = 0; w < 16; w++) tt += red1[w];
        g_partial[base] = tt;
    }
}

// =======================================================================
// k_c: computes t from g_partial (deterministic fixed-order, identical in
// every block), then c[b,o,i] = softmax over o of (t * d[b,o,i]).
// Grid: (Iz/256, Bz). Block 256. d tile staged in smem (stride 257 ->
// conflict-free column reads); low regs -> high occupancy.
// cout == nullptr -> write g_c, else write cout (final output region).
// =======================================================================
__global__ __launch_bounds__(256) void k_c(float* __restrict__ cout)
{
    __shared__ float psum[256];
    __shared__ float tsh;
    __shared__ float dsm[32 * 257];   // 32 o-rows x 256 i, stride 257

    const int tid = threadIdx.x;
    const int b   = blockIdx.y;
    const int i0  = blockIdx.x * 256;

    // ---- prologue: mean(d) -> t (identical fixed-order sum in every block) ----
    {
        float s = 0.f;
        const int j0 = tid * 8;
        #pragma unroll
        for (int j = 0; j < 8; j++) s += g_partial[j0 + j];
        psum[tid] = s;
    }
    __syncthreads();
    if (tid == 0) {
        float tot = 0.f;
        for (int w = 0; w < 256; w++) tot += psum[w];
        float mean = tot / (float)((size_t)Bz * Oz * Iz);
        const float t_const = 5.6312118f;   // ln(279)
        tsh = t_const / (1e-12f - 0.5f * mean);
    }

    // ---- stage d[b, :, i0..i0+255] (coalesced 1KB per o-row) ----
    for (int idx = tid; idx < 32 * 256; idx += 256) {
        int o = idx >> 8, ii = idx & 255;
        dsm[o * 257 + ii] = g_d[((size_t)(b * Oz + o)) * Iz + i0 + ii];
    }
    __syncthreads();

    const float tv = tsh;

    float mx = -1e30f;
    #pragma unroll
    for (int o = 0; o < 32; o++)
        mx = fmaxf(mx, tv * dsm[o * 257 + tid]);

    float ssum = 0.f;
    #pragma unroll
    for (int o = 0; o < 32; o++)
        ssum += expf(tv * dsm[o * 257 + tid] - mx);

    float inv = 1.0f / ssum;
    float* dst = cout ? cout : g_c;
    #pragma unroll
    for (int o = 0; o < 32; o++)
        dst[(size_t)(b * Oz + o) * Iz + i0 + tid] =
            expf(tv * dsm[o * 257 + tid] - mx) * inv;
}

// =======================================================================
// k_s_final: final s/v with c read from the output buffer; writes v to out.
// Grid: (O, B). Block: 512; same load structure as k_sd phase 1.
// =======================================================================
__global__ __launch_bounds__(512, 2) void k_s_final(const float* __restrict__ cext,
                                                    const float* __restrict__ bias,
                                                    float* __restrict__ vext)
{
    const int o = blockIdx.x;
    const int b = blockIdx.y;
    const size_t base = (size_t)(b * Oz + o);
    const float4* uh4 = (const float4*)(g_uhat + base * Dz * Iz);
    const float2* cp2 = (const float2*)(cext + base * Iz);
    const int t = threadIdx.x;

    float acc[16];
    #pragma unroll
    for (int d = 0; d < 16; d++) acc[d] = 0.f;

    #pragma unroll
    for (int jj = 0; jj < 2; jj++) {
        const int j = t + jj * 512;
        float2 cc = cp2[j];
        #pragma unroll
        for (int dg = 0; dg < 8; dg++) {
            float4 x = uh4[dg * 1024 + j];
            acc[2*dg+0] += cc.x * x.x + cc.y * x.z;
            acc[2*dg+1] += cc.x * x.y + cc.y * x.w;
        }
    }

    #pragma unroll
    for (int d = 0; d < 16; d++) {
        #pragma unroll
        for (int off = 16; off > 0; off >>= 1)
            acc[d] += __shfl_down_sync(0xffffffffu, acc[d], off);
    }

    __shared__ float red[16][16];
    const int lane = t & 31;
    const int wid  = t >> 5;
    if (lane == 0) {
        #pragma unroll
        for (int d = 0; d < 16; d++) red[wid][d] = acc[d];
    }
    __syncthreads();

    if (t < 16) {
        const int d = t;
        float tot = 0.f;
        #pragma unroll
        for (int w = 0; w < 16; w++) tot += red[w][d];
        float s = tot + bias[o * Dz + d];

        float n2 = s * s;
        #pragma unroll
        for (int off = 8; off > 0; off >>= 1)
            n2 += __shfl_xor_sync(0x0000ffffu, n2, off);

        vext[(b * Oz + o) * Dz + d] = s * (n2 / ((1.0f + n2) * sqrtf(n2 + 1e-12f)));
    }
}

// =======================================================================
extern "C" void kernel_launch(void* const* d_in, const int* in_sizes, int n_in,
                              void* d_out, int out_size)
{
    const float* u    = (const float*)d_in[0];   // [64, 2048, 16]
    const float* W    = (const float*)d_in[1];   // [1, 32, 2048, 16, 16]
    const float* bias = (const float*)d_in[2];   // [1, 32, 16]

    float* out        = (float*)d_out;
    float* vout_final = out;                     // [64,32,16]
    float* cout_final = out + Bz * Oz * Dz;      // [64,32,2048,1]

    dim3 gUH(Iz / 32, Oz);
    dim3 gBO(Oz, Bz);
    dim3 gC(Iz / 256, Bz);

    k_unorm<<<(Bz * Iz) / 256, 256>>>(u);
    k_uhat<<<gUH, 256>>>(u, W);

    // iteration 0: c uniform; fused s/v + d
    k_sd<<<gBO, 512>>>(0, bias);

    // iteration 1
    k_c<<<gC, 256>>>(nullptr);                   // t + softmax -> g_c
    k_sd<<<gBO, 512>>>(1, bias);

    // iteration 2 (final): c2 and v2 go straight to d_out
    k_c<<<gC, 256>>>(cout_final);                // t + softmax -> out
    k_s_final<<<gBO, 512>>>(cout_final, bias, vout_final);
}

// round 16
// speedup vs baseline: 1.4908x; 1.0257x over previous
#include <cuda_runtime.h>
#include <stdint.h>
#include <math.h>

// Problem constants
#define Bz 64
#define Oz 32
#define Iz 2048
#define Dz 16   // DOUT == DIN == 16

// ---------------- scratch (static device globals; no allocation) ----------------
// u_hat layout: [b][o][d][i]  (i contiguous -> coalesced reads in all 5 reader passes)
__device__ float g_uhat[(size_t)Bz * Oz * Dz * Iz];   // 256 MiB
__device__ float g_d[(size_t)Bz * Oz * Iz];           // distances d[b][o][i]
__device__ float g_c[(size_t)Bz * Oz * Iz];           // routing coeffs (iter-1 scratch)
__device__ float g_partial[Bz * Oz];                  // per-CTA partial sums of d
__device__ float g_unorm[(size_t)Bz * Iz];            // ||u[b,i]|| (precomputed)

// =======================================================================
// k_nop: no-op padding launches so the ncu window (-s 5 -c 1, which
// empirically lands on OUR launch index 3) profiles k_uhat this round.
// =======================================================================
__global__ void k_nop() {}

// =======================================================================
// k_unorm: ||u[b,i]|| for all (b,i). 128K threads, trivially coalesced.
// =======================================================================
__global__ __launch_bounds__(256) void k_unorm(const float* __restrict__ u)
{
    const int idx = blockIdx.x * 256 + threadIdx.x;   // b*Iz + i
    const float4* up = (const float4*)(u + (size_t)idx * 16);
    float n2 = 0.f;
    #pragma unroll
    for (int q = 0; q < 4; q++) {
        float4 t = up[q];
        n2 += t.x*t.x + t.y*t.y + t.z*t.z + t.w*t.w;
    }
    g_unorm[idx] = sqrtf(n2);
}

// =======================================================================
// K1: u_hat[b,o,d,i] = clip( sum_k W[o,i,d,k] * u[b,i,k] )
// Grid: (I/32, O). Block: 256 = 8 warps; lane = il_local*8 + dg.
// W rows for this thread's 2 d's live in REGISTERS (32 floats, loaded once).
// u staged to smem in 16-batch chunks, DOUBLE-BUFFERED via cp.async so the
// chunk bc+1 load overlaps chunk bc compute. Norm over d via 3 shfl_xor in
// the 8-lane dg group. Stores as in R10 (proven best).
// =======================================================================
__device__ __forceinline__ void cp16(float* dst_smem, const float* src_gmem)
{
    unsigned int d = (unsigned int)__cvta_generic_to_shared(dst_smem);
    asm volatile("cp.async.ca.shared.global [%0], [%1], 16;" :: "r"(d), "l"(src_gmem));
}

__global__ __launch_bounds__(256) void k_uhat(const float* __restrict__ u,
                                              const float* __restrict__ W)
{
    // one pool: [0..8191]=ubuf0, [8192..16383]=ubuf1, [16384..16895]=un0,
    // [16896..17407]=un1. W staging aliases [0..8447] (prologue only).
    __shared__ float sall[17408];   // 69.6 KB

    const int o  = blockIdx.y;
    const int i0 = blockIdx.x * 32;
    const int tid  = threadIdx.x;
    const int w    = tid >> 5;
    const int lane = tid & 31;
    const int il_l = lane >> 3;             // 0..3
    const int dg   = lane & 7;              // 0..7 -> d rows 2dg, 2dg+1
    const int il   = w * 4 + il_l;          // 0..31
    const int i    = i0 + il;

    // ---- stage W[o, i0..i0+31, :, :] (8192 contiguous floats), coalesced ----
    const float* Wg = W + ((size_t)o * Iz + i0) * 256;
    for (int idx = tid; idx < 8192; idx += 256) {
        int ils = idx >> 8, j = idx & 255;
        sall[ils * 264 + j] = Wg[idx];
    }
    __syncthreads();

    // ---- pull this thread's 2 W rows into registers ----
    float wA[16], wB[16];
    {
        const float* r0 = &sall[il * 264 + (2 * dg) * 16];
        const float* r1 = r0 + 16;
        #pragma unroll
        for (int q = 0; q < 4; q++) {
            float4 a = *(const float4*)(r0 + q * 4);
            float4 b = *(const float4*)(r1 + q * 4);
            wA[q*4+0] = a.x; wA[q*4+1] = a.y; wA[q*4+2] = a.z; wA[q*4+3] = a.w;
            wB[q*4+0] = b.x; wB[q*4+1] = b.y; wB[q*4+2] = b.z; wB[q*4+3] = b.w;
        }
    }
    __syncthreads();   // everyone done reading W before cp.async overwrites it

    float* ubuf[2] = { sall,         sall + 8192  };
    float* unbf[2] = { sall + 16384, sall + 16896 };

    // ---- prefetch chunk 0 ----
    {
        const float* ug = u + ((size_t)0 * Iz + i0) * 16;
        for (int idx4 = tid; idx4 < 2048; idx4 += 256) {
            int bl = idx4 >> 7, r4 = idx4 & 127;
            cp16(ubuf[0] + bl * 512 + r4 * 4, ug + (size_t)bl * Iz * 16 + r4 * 4);
        }
        if (tid < 128) {
            int bl = tid >> 3, ii4 = tid & 7;
            cp16(unbf[0] + bl * 32 + ii4 * 4, g_unorm + (size_t)bl * Iz + i0 + ii4 * 4);
        }
        asm volatile("cp.async.commit_group;");
    }

    // ---- 4 chunks of 16 batches, double-buffered ----
    for (int bc = 0; bc < 4; bc++) {
        const float* cb = ubuf[bc & 1];
        const float* un = unbf[bc & 1];

        if (bc < 3) {
            const int nb = bc + 1;
            const float* ug = u + ((size_t)(nb * 16) * Iz + i0) * 16;
            float* db = ubuf[nb & 1];
            float* dn = unbf[nb & 1];
            for (int idx4 = tid; idx4 < 2048; idx4 += 256) {
                int bl = idx4 >> 7, r4 = idx4 & 127;
                cp16(db + bl * 512 + r4 * 4, ug + (size_t)bl * Iz * 16 + r4 * 4);
            }
            if (tid < 128) {
                int bl = tid >> 3, ii4 = tid & 7;
                cp16(dn + bl * 32 + ii4 * 4,
                     g_unorm + (size_t)(nb * 16 + bl) * Iz + i0 + ii4 * 4);
            }
            asm volatile("cp.async.commit_group;");
            asm volatile("cp.async.wait_group 1;");   // chunk bc arrived
        } else {
            asm volatile("cp.async.wait_group 0;");
        }
        __syncthreads();

        #pragma unroll 4
        for (int bl = 0; bl < 16; bl++) {
            const float* ub = &cb[bl * 512 + il * 16];   // 8-lane broadcast reads
            float4 u0 = *(const float4*)(ub + 0);
            float4 u1 = *(const float4*)(ub + 4);
            float4 u2 = *(const float4*)(ub + 8);
            float4 u3 = *(const float4*)(ub + 12);
            float uu[16] = {u0.x,u0.y,u0.z,u0.w, u1.x,u1.y,u1.z,u1.w,
                            u2.x,u2.y,u2.z,u2.w, u3.x,u3.y,u3.z,u3.w};

            float a0 = 0.f, a1 = 0.f;
            #pragma unroll
            for (int k = 0; k < 16; k++) {
                a0 += wA[k] * uu[k];
                a1 += wB[k] * uu[k];
            }

            // ||u_hat||^2 over all 16 d: reduce across the 8 dg lanes
            float n2 = a0 * a0 + a1 * a1;
            n2 += __shfl_xor_sync(0xffffffffu, n2, 1);
            n2 += __shfl_xor_sync(0xffffffffu, n2, 2);
            n2 += __shfl_xor_sync(0xffffffffu, n2, 4);

            float nh = sqrtf(n2);
            float nu = un[bl * 32 + il];
            float sc = fminf(nh, nu) / (nh + 1e-12f);

            const int b = bc * 16 + bl;
            float* dst = g_uhat + ((size_t)(b * Oz + o) * Dz + 2 * dg) * Iz + i;
            dst[0]  = a0 * sc;
            dst[Iz] = a1 * sc;
        }
        __syncthreads();   // before buffer (bc&1) is re-filled at bc+2
    }
}

// =======================================================================
// k_sd: FUSED s/v + distance (R10-proven). Phase 1 reads u_hat from DRAM,
// phase 2 re-reads from L2. mode 0: c = 1/O ; mode 1: c = g_c.
// Grid: (O, B). Block: 512 (each thread owns 4 consecutive i via float4).
// =======================================================================
__global__ __launch_bounds__(512, 2) void k_sd(int mode, const float* __restrict__ bias)
{
    const int o = blockIdx.x;
    const int b = blockIdx.y;
    const size_t base = (size_t)(b * Oz + o);
    const float4* uh4 = (const float4*)(g_uhat + base * Dz * Iz);
    const int t = threadIdx.x;

    // ---- phase 1: s accumulation ----
    float4 cc;
    if (mode == 0) cc = make_float4(1.f/32.f, 1.f/32.f, 1.f/32.f, 1.f/32.f);
    else           cc = ((const float4*)(g_c + base * Iz))[t];

    float acc[16];
    #pragma unroll
    for (int d = 0; d < 16; d++) {
        float4 x = uh4[d * 512 + t];
        acc[d] = cc.x*x.x + cc.y*x.y + cc.z*x.z + cc.w*x.w;
    }

    #pragma unroll
    for (int d = 0; d < 16; d++) {
        #pragma unroll
        for (int off = 16; off > 0; off >>= 1)
            acc[d] += __shfl_down_sync(0xffffffffu, acc[d], off);
    }

    __shared__ float red[16][16];
    __shared__ float vsm[16];
    const int lane = t & 31;
    const int wid  = t >> 5;
    if (lane == 0) {
        #pragma unroll
        for (int d = 0; d < 16; d++) red[wid][d] = acc[d];
    }
    __syncthreads();

    if (t < 16) {
        const int d = t;
        float tot = 0.f;
        #pragma unroll
        for (int w = 0; w < 16; w++) tot += red[w][d];
        float s = tot + bias[o * Dz + d];

        float n2 = s * s;
        #pragma unroll
        for (int off = 8; off > 0; off >>= 1)
            n2 += __shfl_xor_sync(0x0000ffffu, n2, off);

        vsm[d] = s * (n2 / ((1.0f + n2) * sqrtf(n2 + 1e-12f)));
    }
    __syncthreads();

    // ---- phase 2: distances (u_hat re-read hits L2) ----
    float4 s2 = make_float4(0.f, 0.f, 0.f, 0.f);
    #pragma unroll
    for (int d = 0; d < 16; d++) {
        float vd = vsm[d];
        float4 x = uh4[d * 512 + t];
        float dx = vd - x.x, dy = vd - x.y, dz = vd - x.z, dw = vd - x.w;
        s2.x += dx*dx; s2.y += dy*dy; s2.z += dz*dz; s2.w += dw*dw;
    }
    float4 dd = make_float4(sqrtf(s2.x), sqrtf(s2.y), sqrtf(s2.z), sqrtf(s2.w));
    ((float4*)(g_d + base * Iz))[t] = dd;

    float lsum = (dd.x + dd.y) + (dd.z + dd.w);
    #pragma unroll
    for (int off = 16; off > 0; off >>= 1)
        lsum += __shfl_down_sync(0xffffffffu, lsum, off);

    __shared__ float red1[16];
    if (lane == 0) red1[wid] = lsum;
    __syncthreads();
    if (t == 0) {
        float tt = 0.f;
        #pragma unroll
        for (int w = 0; w < 16; w++) tt += red1[w];
        g_partial[base] = tt;
    }
}

// =======================================================================
// k_c (R10-proven): t from g_partial (deterministic fixed-order), then
// c[b,o,i] = softmax over o of (t * d[b,o,i]).
// =======================================================================
__global__ __launch_bounds__(256, 1) void k_c(float* __restrict__ cout)
{
    __shared__ float psum[256];
    __shared__ float tsh;
    {
        float s = 0.f;
        const int j0 = threadIdx.x * 8;
        #pragma unroll
        for (int j = 0; j < 8; j++) s += g_partial[j0 + j];
        psum[threadIdx.x] = s;
    }
    __syncthreads();
    if (threadIdx.x == 0) {
        float tot = 0.f;
        for (int w = 0; w < 256; w++) tot += psum[w];
        float mean = tot / (float)((size_t)Bz * Oz * Iz);
        const float t_const = 5.6312118f;   // ln(279)
        tsh = t_const / (1e-12f - 0.5f * mean);
    }
    __syncthreads();
    const float t = tsh;

    const int idx = blockIdx.x * 256 + threadIdx.x;
    const int b = idx >> 11;
    const int i = idx & (Iz - 1);

    float vals[32];
    float mx = -1e30f;
    #pragma unroll
    for (int o = 0; o < 32; o++) {
        float x = t * g_d[(size_t)(b * Oz + o) * Iz + i];
        vals[o] = x;
        mx = fmaxf(mx, x);
    }
    float ssum = 0.f;
    #pragma unroll
    for (int o = 0; o < 32; o++) {
        float e = expf(vals[o] - mx);
        vals[o] = e;
        ssum += e;
    }
    float inv = 1.0f / ssum;
    float* dst = cout ? cout : g_c;
    #pragma unroll
    for (int o = 0; o < 32; o++)
        dst[(size_t)(b * Oz + o) * Iz + i] = vals[o] * inv;
}

// =======================================================================
// k_s_final (R10-proven): final s/v with c from the output buffer.
// =======================================================================
__global__ __launch_bounds__(512, 2) void k_s_final(const float* __restrict__ cext,
                                                    const float* __restrict__ bias,
                                                    float* __restrict__ vext)
{
    const int o = blockIdx.x;
    const int b = blockIdx.y;
    const size_t base = (size_t)(b * Oz + o);
    const float4* uh4 = (const float4*)(g_uhat + base * Dz * Iz);
    const int t = threadIdx.x;

    float4 cc = ((const float4*)(cext + base * Iz))[t];

    float acc[16];
    #pragma unroll
    for (int d = 0; d < 16; d++) {
        float4 x = uh4[d * 512 + t];
        acc[d] = cc.x*x.x + cc.y*x.y + cc.z*x.z + cc.w*x.w;
    }

    #pragma unroll
    for (int d = 0; d < 16; d++) {
        #pragma unroll
        for (int off = 16; off > 0; off >>= 1)
            acc[d] += __shfl_down_sync(0xffffffffu, acc[d], off);
    }

    __shared__ float red[16][16];
    const int lane = t & 31;
    const int wid  = t >> 5;
    if (lane == 0) {
        #pragma unroll
        for (int d = 0; d < 16; d++) red[wid][d] = acc[d];
    }
    __syncthreads();

    if (t < 16) {
        const int d = t;
        float tot = 0.f;
        #pragma unroll
        for (int w = 0; w < 16; w++) tot += red[w][d];
        float s = tot + bias[o * Dz + d];

        float n2 = s * s;
        #pragma unroll
        for (int off = 8; off > 0; off >>= 1)
            n2 += __shfl_xor_sync(0x0000ffffu, n2, off);

        vext[(b * Oz + o) * Dz + d] = s * (n2 / ((1.0f + n2) * sqrtf(n2 + 1e-12f)));
    }
}

// =======================================================================
extern "C" void kernel_launch(void* const* d_in, const int* in_sizes, int n_in,
                              void* d_out, int out_size)
{
    const float* u    = (const float*)d_in[0];   // [64, 2048, 16]
    const float* W    = (const float*)d_in[1];   // [1, 32, 2048, 16, 16]
    const float* bias = (const float*)d_in[2];   // [1, 32, 16]

    float* out        = (float*)d_out;
    float* vout_final = out;                     // [64,32,16]
    float* cout_final = out + Bz * Oz * Dz;      // [64,32,2048,1]

    dim3 gUH(Iz / 32, Oz);
    dim3 gBO(Oz, Bz);

    // padding so k_uhat sits at launch index 3 (the profiled slot)
    k_nop<<<1, 32>>>();
    k_nop<<<1, 32>>>();

    k_unorm<<<(Bz * Iz) / 256, 256>>>(u);
    k_uhat<<<gUH, 256>>>(u, W);                  // <- profiled this round

    // iteration 0: c uniform; fused s/v + d
    k_sd<<<gBO, 512>>>(0, bias);

    // iteration 1
    k_c<<<(Bz * Iz) / 256, 256>>>(nullptr);      // t + softmax -> g_c
    k_sd<<<gBO, 512>>>(1, bias);

    // iteration 2 (final): c2 and v2 go straight to d_out
    k_c<<<(Bz * Iz) / 256, 256>>>(cout_final);   // t + softmax -> out
    k_s_final<<<gBO, 512>>>(cout_final, bias, vout_final);
}

// round 17
// speedup vs baseline: 1.6021x; 1.0747x over previous
#include <cuda_runtime.h>
#include <stdint.h>
#include <math.h>

// Problem constants
#define Bz 64
#define Oz 32
#define Iz 2048
#define Dz 16   // DOUT == DIN == 16

// ---------------- scratch (static device globals; no allocation) ----------------
// u_hat layout: [b][o][d][i]  (i contiguous -> coalesced reads in all 5 reader passes)
__device__ float g_uhat[(size_t)Bz * Oz * Dz * Iz];   // 256 MiB
__device__ float g_d[(size_t)Bz * Oz * Iz];           // distances d[b][o][i]
__device__ float g_c[(size_t)Bz * Oz * Iz];           // routing coeffs (iter-1 scratch)
__device__ float g_partial[Bz * Oz];                  // per-CTA partial sums of d
__device__ float g_unorm[(size_t)Bz * Iz];            // ||u[b,i]|| (precomputed)

// =======================================================================
// k_nop: padding so k_uhat stays at the profiled launch index (3).
// =======================================================================
__global__ void k_nop() {}

// =======================================================================
// k_unorm: ||u[b,i]|| for all (b,i). 128K threads, trivially coalesced.
// =======================================================================
__global__ __launch_bounds__(256) void k_unorm(const float* __restrict__ u)
{
    const int idx = blockIdx.x * 256 + threadIdx.x;   // b*Iz + i
    const float4* up = (const float4*)(u + (size_t)idx * 16);
    float n2 = 0.f;
    #pragma unroll
    for (int q = 0; q < 4; q++) {
        float4 t = up[q];
        n2 += t.x*t.x + t.y*t.y + t.z*t.z + t.w*t.w;
    }
    g_unorm[idx] = sqrtf(n2);
}

// =======================================================================
// K1: u_hat[b,o,d,i] = clip( sum_k W[o,i,d,k] * u[b,i,k] )
// Grid: (I/32, O). Block: 256 = 8 warps; lane = il_local*8 + dg.
// W rows for this thread's 2 d's live in REGISTERS (32 floats, loaded once).
// u staged to smem in 16-batch chunks (synchronous — cp.async was disproven).
// LATENCY FIX vs R10: inner loop processes 4 batches as a group — FFMA for
// all 4 first, then 3 shfl rounds over 4 INDEPENDENT chains (latency
// overlapped 4x), then 4 independent sqrt/div/store tails.
// =======================================================================
__global__ __launch_bounds__(256) void k_uhat(const float* __restrict__ u,
                                              const float* __restrict__ W)
{
    __shared__ float pool[32 * 264];        // 33.8 KB: W staging, then u chunks
    __shared__ float un_sm[512];            // ||u|| for current chunk (16b x 32i)

    const int o  = blockIdx.y;
    const int i0 = blockIdx.x * 32;
    const int tid  = threadIdx.x;
    const int w    = tid >> 5;
    const int lane = tid & 31;
    const int il_l = lane >> 3;             // 0..3
    const int dg   = lane & 7;              // 0..7 -> d rows 2dg, 2dg+1
    const int il   = w * 4 + il_l;          // 0..31
    const int i    = i0 + il;

    // ---- stage W[o, i0..i0+31, :, :] (8192 contiguous floats), coalesced ----
    const float* Wg = W + ((size_t)o * Iz + i0) * 256;
    for (int idx = tid; idx < 8192; idx += 256) {
        int ils = idx >> 8, j = idx & 255;
        pool[ils * 264 + j] = Wg[idx];
    }
    __syncthreads();

    // ---- pull this thread's 2 W rows into registers ----
    float wA[16], wB[16];
    {
        const float* r0 = &pool[il * 264 + (2 * dg) * 16];
        const float* r1 = r0 + 16;
        #pragma unroll
        for (int q = 0; q < 4; q++) {
            float4 a = *(const float4*)(r0 + q * 4);
            float4 b = *(const float4*)(r1 + q * 4);
            wA[q*4+0] = a.x; wA[q*4+1] = a.y; wA[q*4+2] = a.z; wA[q*4+3] = a.w;
            wB[q*4+0] = b.x; wB[q*4+1] = b.y; wB[q*4+2] = b.z; wB[q*4+3] = b.w;
        }
    }
    __syncthreads();   // everyone done reading W before u overwrites pool

    // ---- 4 chunks of 16 batches ----
    for (int bc = 0; bc < 4; bc++) {
        // stage u[bc*16 .. bc*16+15][i0..i0+31][:] : 16 x 512 contiguous floats
        const float* ug = u + ((size_t)(bc * 16) * Iz + i0) * 16;
        for (int idx = tid; idx < 8192; idx += 256) {
            int bl = idx >> 9, r = idx & 511;
            pool[bl * 512 + r] = ug[(size_t)bl * Iz * 16 + r];
        }
        // stage ||u|| for this chunk (512 entries, 256 threads -> 2 per thread)
        for (int idx = tid; idx < 512; idx += 256) {
            int bl = idx >> 5, ii = idx & 31;
            un_sm[idx] = g_unorm[(size_t)(bc * 16 + bl) * Iz + i0 + ii];
        }
        __syncthreads();

        // ---- 4 groups of 4 batches: batched math, then batched reductions ----
        for (int bg = 0; bg < 4; bg++) {
            float A0[4], A1[4], nn[4];

            #pragma unroll
            for (int q = 0; q < 4; q++) {
                const int bl = bg * 4 + q;
                const float* ub = &pool[bl * 512 + il * 16];   // broadcast reads
                float4 u0 = *(const float4*)(ub + 0);
                float4 u1 = *(const float4*)(ub + 4);
                float4 u2 = *(const float4*)(ub + 8);
                float4 u3 = *(const float4*)(ub + 12);
                float uu[16] = {u0.x,u0.y,u0.z,u0.w, u1.x,u1.y,u1.z,u1.w,
                                u2.x,u2.y,u2.z,u2.w, u3.x,u3.y,u3.z,u3.w};

                float a0 = 0.f, a1 = 0.f;
                #pragma unroll
                for (int k = 0; k < 16; k++) {
                    a0 += wA[k] * uu[k];
                    a1 += wB[k] * uu[k];
                }
                A0[q] = a0; A1[q] = a1;
                nn[q] = a0 * a0 + a1 * a1;
            }

            // 3 shfl rounds, 4 independent chains -> latency overlapped
            #pragma unroll
            for (int m = 1; m <= 4; m <<= 1) {
                #pragma unroll
                for (int q = 0; q < 4; q++)
                    nn[q] += __shfl_xor_sync(0xffffffffu, nn[q], m);
            }

            #pragma unroll
            for (int q = 0; q < 4; q++) {
                const int bl = bg * 4 + q;
                float nh = sqrtf(nn[q]);
                float nu = un_sm[bl * 32 + il];
                float sc = fminf(nh, nu) / (nh + 1e-12f);

                const int b = bc * 16 + bl;
                float* dst = g_uhat + ((size_t)(b * Oz + o) * Dz + 2 * dg) * Iz + i;
                dst[0]  = A0[q] * sc;
                dst[Iz] = A1[q] * sc;
            }
        }
        __syncthreads();   // before next chunk overwrites pool
    }
}

// =======================================================================
// k_sd: FUSED s/v + distance (R10-proven). Phase 1 reads u_hat from DRAM,
// phase 2 re-reads from L2. mode 0: c = 1/O ; mode 1: c = g_c.
// Grid: (O, B). Block: 512 (each thread owns 4 consecutive i via float4).
// =======================================================================
__global__ __launch_bounds__(512, 2) void k_sd(int mode, const float* __restrict__ bias)
{
    const int o = blockIdx.x;
    const int b = blockIdx.y;
    const size_t base = (size_t)(b * Oz + o);
    const float4* uh4 = (const float4*)(g_uhat + base * Dz * Iz);
    const int t = threadIdx.x;

    // ---- phase 1: s accumulation ----
    float4 cc;
    if (mode == 0) cc = make_float4(1.f/32.f, 1.f/32.f, 1.f/32.f, 1.f/32.f);
    else           cc = ((const float4*)(g_c + base * Iz))[t];

    float acc[16];
    #pragma unroll
    for (int d = 0; d < 16; d++) {
        float4 x = uh4[d * 512 + t];
        acc[d] = cc.x*x.x + cc.y*x.y + cc.z*x.z + cc.w*x.w;
    }

    #pragma unroll
    for (int d = 0; d < 16; d++) {
        #pragma unroll
        for (int off = 16; off > 0; off >>= 1)
            acc[d] += __shfl_down_sync(0xffffffffu, acc[d], off);
    }

    __shared__ float red[16][16];
    __shared__ float vsm[16];
    const int lane = t & 31;
    const int wid  = t >> 5;
    if (lane == 0) {
        #pragma unroll
        for (int d = 0; d < 16; d++) red[wid][d] = acc[d];
    }
    __syncthreads();

    if (t < 16) {
        const int d = t;
        float tot = 0.f;
        #pragma unroll
        for (int w = 0; w < 16; w++) tot += red[w][d];
        float s = tot + bias[o * Dz + d];

        float n2 = s * s;
        #pragma unroll
        for (int off = 8; off > 0; off >>= 1)
            n2 += __shfl_xor_sync(0x0000ffffu, n2, off);

        vsm[d] = s * (n2 / ((1.0f + n2) * sqrtf(n2 + 1e-12f)));
    }
    __syncthreads();

    // ---- phase 2: distances (u_hat re-read hits L2) ----
    float4 s2 = make_float4(0.f, 0.f, 0.f, 0.f);
    #pragma unroll
    for (int d = 0; d < 16; d++) {
        float vd = vsm[d];
        float4 x = uh4[d * 512 + t];
        float dx = vd - x.x, dy = vd - x.y, dz = vd - x.z, dw = vd - x.w;
        s2.x += dx*dx; s2.y += dy*dy; s2.z += dz*dz; s2.w += dw*dw;
    }
    float4 dd = make_float4(sqrtf(s2.x), sqrtf(s2.y), sqrtf(s2.z), sqrtf(s2.w));
    ((float4*)(g_d + base * Iz))[t] = dd;

    float lsum = (dd.x + dd.y) + (dd.z + dd.w);
    #pragma unroll
    for (int off = 16; off > 0; off >>= 1)
        lsum += __shfl_down_sync(0xffffffffu, lsum, off);

    __shared__ float red1[16];
    if (lane == 0) red1[wid] = lsum;
    __syncthreads();
    if (t == 0) {
        float tt = 0.f;
        #pragma unroll
        for (int w = 0; w < 16; w++) tt += red1[w];
        g_partial[base] = tt;
    }
}

// =======================================================================
// k_c (R10-proven): t from g_partial (deterministic fixed-order), then
// c[b,o,i] = softmax over o of (t * d[b,o,i]).
// =======================================================================
__global__ __launch_bounds__(256, 1) void k_c(float* __restrict__ cout)
{
    __shared__ float psum[256];
    __shared__ float tsh;
    {
        float s = 0.f;
        const int j0 = threadIdx.x * 8;
        #pragma unroll
        for (int j = 0; j < 8; j++) s += g_partial[j0 + j];
        psum[threadIdx.x] = s;
    }
    __syncthreads();
    if (threadIdx.x == 0) {
        float tot = 0.f;
        for (int w = 0; w < 256; w++) tot += psum[w];
        float mean = tot / (float)((size_t)Bz * Oz * Iz);
        const float t_const = 5.6312118f;   // ln(279)
        tsh = t_const / (1e-12f - 0.5f * mean);
    }
    __syncthreads();
    const float t = tsh;

    const int idx = blockIdx.x * 256 + threadIdx.x;
    const int b = idx >> 11;
    const int i = idx & (Iz - 1);

    float vals[32];
    float mx = -1e30f;
    #pragma unroll
    for (int o = 0; o < 32; o++) {
        float x = t * g_d[(size_t)(b * Oz + o) * Iz + i];
        vals[o] = x;
        mx = fmaxf(mx, x);
    }
    float ssum = 0.f;
    #pragma unroll
    for (int o = 0; o < 32; o++) {
        float e = expf(vals[o] - mx);
        vals[o] = e;
        ssum += e;
    }
    float inv = 1.0f / ssum;
    float* dst = cout ? cout : g_c;
    #pragma unroll
    for (int o = 0; o < 32; o++)
        dst[(size_t)(b * Oz + o) * Iz + i] = vals[o] * inv;
}

// =======================================================================
// k_s_final (R10-proven): final s/v with c from the output buffer.
// =======================================================================
__global__ __launch_bounds__(512, 2) void k_s_final(const float* __restrict__ cext,
                                                    const float* __restrict__ bias,
                                                    float* __restrict__ vext)
{
    const int o = blockIdx.x;
    const int b = blockIdx.y;
    const size_t base = (size_t)(b * Oz + o);
    const float4* uh4 = (const float4*)(g_uhat + base * Dz * Iz);
    const int t = threadIdx.x;

    float4 cc = ((const float4*)(cext + base * Iz))[t];

    float acc[16];
    #pragma unroll
    for (int d = 0; d < 16; d++) {
        float4 x = uh4[d * 512 + t];
        acc[d] = cc.x*x.x + cc.y*x.y + cc.z*x.z + cc.w*x.w;
    }

    #pragma unroll
    for (int d = 0; d < 16; d++) {
        #pragma unroll
        for (int off = 16; off > 0; off >>= 1)
            acc[d] += __shfl_down_sync(0xffffffffu, acc[d], off);
    }

    __shared__ float red[16][16];
    const int lane = t & 31;
    const int wid  = t >> 5;
    if (lane == 0) {
        #pragma unroll
        for (int d = 0; d < 16; d++) red[wid][d] = acc[d];
    }
    __syncthreads();

    if (t < 16) {
        const int d = t;
        float tot = 0.f;
        #pragma unroll
        for (int w = 0; w < 16; w++) tot += red[w][d];
        float s = tot + bias[o * Dz + d];

        float n2 = s * s;
        #pragma unroll
        for (int off = 8; off > 0; off >>= 1)
            n2 += __shfl_xor_sync(0x0000ffffu, n2, off);

        vext[(b * Oz + o) * Dz + d] = s * (n2 / ((1.0f + n2) * sqrtf(n2 + 1e-12f)));
    }
}

// =======================================================================
extern "C" void kernel_launch(void* const* d_in, const int* in_sizes, int n_in,
                              void* d_out, int out_size)
{
    const float* u    = (const float*)d_in[0];   // [64, 2048, 16]
    const float* W    = (const float*)d_in[1];   // [1, 32, 2048, 16, 16]
    const float* bias = (const float*)d_in[2];   // [1, 32, 16]

    float* out        = (float*)d_out;
    float* vout_final = out;                     // [64,32,16]
    float* cout_final = out + Bz * Oz * Dz;      // [64,32,2048,1]

    dim3 gUH(Iz / 32, Oz);
    dim3 gBO(Oz, Bz);

    // padding so k_uhat sits at launch index 3 (the profiled slot)
    k_nop<<<1, 32>>>();
    k_nop<<<1, 32>>>();

    k_unorm<<<(Bz * Iz) / 256, 256>>>(u);
    k_uhat<<<gUH, 256>>>(u, W);                  // <- profiled

    // iteration 0: c uniform; fused s/v + d
    k_sd<<<gBO, 512>>>(0, bias);

    // iteration 1
    k_c<<<(Bz * Iz) / 256, 256>>>(nullptr);      // t + softmax -> g_c
    k_sd<<<gBO, 512>>>(1, bias);

    // iteration 2 (final): c2 and v2 go straight to d_out
    k_c<<<(Bz * Iz) / 256, 256>>>(cout_final);   // t + softmax -> out
    k_s_final<<<gBO, 512>>>(cout_final, bias, vout_final);
}